// round 5
// baseline (speedup 1.0000x reference)
#include <cuda_runtime.h>
#include <cstdint>

// Problem dims
#define ROWS   8192        // B*T = 16*512
#define FEAT   2048
#define HID    1024
#define GI_N   3072        // 3*HID
#define NSEQ   128         // B*grn = 16*8
#define NSTEP  64
#define NCLS   21

// Scratch (static device globals — allowed)
__device__ float g_gi[ROWS * GI_N];                    // 96 MB
__device__ float g_hall[(NSTEP + 1) * NSEQ * HID];     // 34 MB, slot 0 = h0 (zeros)

__device__ __forceinline__ float sigmoidf_(float x) { return 1.0f / (1.0f + expf(-x)); }

// ======================= big SGEMM: C = A[M,K] @ W[N,K]^T + bias (opt ReLU) ==================
template<bool RELU>
__global__ __launch_bounds__(256) void sgemm_kernel(
    const float* __restrict__ A, const float* __restrict__ W,
    const float* __restrict__ bias, float* __restrict__ C,
    int M, int N, int K)
{
    __shared__ float As[16][128];
    __shared__ float Ws[16][128];
    const int tid = threadIdx.x;
    const int tx = tid & 15;
    const int ty = tid >> 4;
    const int m0 = blockIdx.y * 128;
    const int n0 = blockIdx.x * 128;
    const float* Ab = A + (size_t)m0 * K;
    const float* Wb = W + (size_t)n0 * K;
    float acc[8][8];
#pragma unroll
    for (int i = 0; i < 8; i++)
#pragma unroll
        for (int j = 0; j < 8; j++) acc[i][j] = 0.0f;

    for (int kc = 0; kc < K; kc += 16) {
#pragma unroll
        for (int jj = 0; jj < 2; jj++) {
            int id = tid + jj * 256;      // 0..511
            int row = id >> 2;            // 0..127
            int q = id & 3;               // which float4 of 16 k's
            float4 va = *(const float4*)(Ab + (size_t)row * K + kc + q * 4);
            As[q*4+0][row] = va.x; As[q*4+1][row] = va.y;
            As[q*4+2][row] = va.z; As[q*4+3][row] = va.w;
            float4 vw = *(const float4*)(Wb + (size_t)row * K + kc + q * 4);
            Ws[q*4+0][row] = vw.x; Ws[q*4+1][row] = vw.y;
            Ws[q*4+2][row] = vw.z; Ws[q*4+3][row] = vw.w;
        }
        __syncthreads();
#pragma unroll
        for (int kk = 0; kk < 16; kk++) {
            float a[8], w[8];
            *(float4*)(a)     = *(const float4*)&As[kk][ty * 8];
            *(float4*)(a + 4) = *(const float4*)&As[kk][ty * 8 + 4];
            *(float4*)(w)     = *(const float4*)&Ws[kk][tx * 8];
            *(float4*)(w + 4) = *(const float4*)&Ws[kk][tx * 8 + 4];
#pragma unroll
            for (int i = 0; i < 8; i++)
#pragma unroll
                for (int j = 0; j < 8; j++)
                    acc[i][j] += a[i] * w[j];
        }
        __syncthreads();
    }

#pragma unroll
    for (int i = 0; i < 8; i++) {
        int m = m0 + ty * 8 + i;
        float* Crow = C + (size_t)m * N;
#pragma unroll
        for (int j4 = 0; j4 < 2; j4++) {
            int n = n0 + tx * 8 + j4 * 4;
            float4 r;
            r.x = acc[i][j4*4+0] + bias[n+0];
            r.y = acc[i][j4*4+1] + bias[n+1];
            r.z = acc[i][j4*4+2] + bias[n+2];
            r.w = acc[i][j4*4+3] + bias[n+3];
            if (RELU) {
                r.x = fmaxf(r.x, 0.0f); r.y = fmaxf(r.y, 0.0f);
                r.z = fmaxf(r.z, 0.0f); r.w = fmaxf(r.w, 0.0f);
            }
            *(float4*)(Crow + n) = r;
        }
    }
}

// ======================= threefry2x32 core (key = (0,42)) ====================================
__device__ __forceinline__ void threefry_0_42(unsigned int c0, unsigned int c1,
                                              unsigned int& o0, unsigned int& o1)
{
    const unsigned int ks0 = 0u;
    const unsigned int ks1 = 42u;
    const unsigned int ks2 = 0u ^ 42u ^ 0x1BD11BDAu;
    unsigned int x0 = c0 + ks0;
    unsigned int x1 = c1 + ks1;
#define TFR(r) { x0 += x1; x1 = (x1 << (r)) | (x1 >> (32 - (r))); x1 ^= x0; }
    TFR(13) TFR(15) TFR(26) TFR(6)
    x0 += ks1; x1 += ks2 + 1u;
    TFR(17) TFR(29) TFR(16) TFR(24)
    x0 += ks2; x1 += ks0 + 2u;
    TFR(13) TFR(15) TFR(26) TFR(6)
    x0 += ks0; x1 += ks1 + 3u;
    TFR(17) TFR(29) TFR(16) TFR(24)
    x0 += ks1; x1 += ks2 + 4u;
    TFR(13) TFR(15) TFR(26) TFR(6)
    x0 += ks2; x1 += ks0 + 5u;
#undef TFR
    o0 = x0; o1 = x1;
}

// ===== JAX partitionable-threefry dropout (VALIDATED by R4 diagnostic) =====
// bits[i] = o0 ^ o1 of threefry2x32(key=(0,42), count=(0, i));  keep if u < 0.7
__global__ __launch_bounds__(256) void dropout_kernel(float* __restrict__ x)
{
    const unsigned int g = blockIdx.x * 256u + threadIdx.x;   // 0 .. 2^22-1
    const unsigned int base = g * 4u;

    float4 v = *(float4*)(x + base);
    float vin[4] = {v.x, v.y, v.z, v.w};
    float vout[4];

#pragma unroll
    for (int e = 0; e < 4; e++) {
        unsigned int o0, o1;
        threefry_0_42(0u, base + e, o0, o1);
        unsigned int bits = o0 ^ o1;
        float u = __uint_as_float((bits >> 9) | 0x3f800000u) - 1.0f;
        vout[e] = (u < 0.7f) ? vin[e] * (1.0f / 0.7f) : 0.0f;
    }
    *(float4*)(x + base) = make_float4(vout[0], vout[1], vout[2], vout[3]);
}

// ======================= GRU step: h_{t+1} from h_t (fused gh GEMM + gates) ===================
__global__ __launch_bounds__(256) void gru_step_kernel(
    const float* __restrict__ gi,    // [8192][3072] (includes b_ih)
    const float* __restrict__ whh,   // [3072][1024]
    const float* __restrict__ bhh,   // [3072]
    int t)
{
    __shared__ float hs[32][65];   // [k][row]
    __shared__ float ws[48][33];   // [gate_col][k]
    const int tid = threadIdx.x;
    const int tx = tid & 15;       // local unit
    const int ty = tid >> 4;       // row group (4 rows each)
    const int u0 = blockIdx.x * 16;
    const int m0 = blockIdx.y * 64;

    const float* hprev = g_hall + (size_t)t * NSEQ * HID;
    float* hout        = g_hall + (size_t)(t + 1) * NSEQ * HID;

    float acc0[4] = {0.f,0.f,0.f,0.f};
    float acc1[4] = {0.f,0.f,0.f,0.f};
    float acc2[4] = {0.f,0.f,0.f,0.f};

    for (int kc = 0; kc < HID; kc += 32) {
#pragma unroll
        for (int jj = 0; jj < 2; jj++) {
            int id = tid + jj * 256;
            int row = id >> 3;
            int q = id & 7;
            float4 v = *(const float4*)(hprev + (size_t)(m0 + row) * HID + kc + q * 4);
            hs[q*4+0][row] = v.x; hs[q*4+1][row] = v.y;
            hs[q*4+2][row] = v.z; hs[q*4+3][row] = v.w;
        }
#pragma unroll
        for (int jj = 0; jj < 2; jj++) {
            int id = tid + jj * 256;
            if (id < 384) {
                int gcol = id >> 3;          // 0..47
                int q = id & 7;
                int grow = (gcol >> 4) * HID + u0 + (gcol & 15);  // gate*1024 + unit
                float4 v = *(const float4*)(whh + (size_t)grow * HID + kc + q * 4);
                ws[gcol][q*4+0] = v.x; ws[gcol][q*4+1] = v.y;
                ws[gcol][q*4+2] = v.z; ws[gcol][q*4+3] = v.w;
            }
        }
        __syncthreads();
#pragma unroll
        for (int kk = 0; kk < 32; kk++) {
            float w0 = ws[tx][kk];
            float w1 = ws[16 + tx][kk];
            float w2 = ws[32 + tx][kk];
#pragma unroll
            for (int i = 0; i < 4; i++) {
                float h = hs[kk][(ty << 2) + i];
                acc0[i] += w0 * h;
                acc1[i] += w1 * h;
                acc2[i] += w2 * h;
            }
        }
        __syncthreads();
    }

    const int unit = u0 + tx;
    const float br = bhh[unit];
    const float bz = bhh[HID + unit];
    const float bn = bhh[2 * HID + unit];
#pragma unroll
    for (int i = 0; i < 4; i++) {
        int n = m0 + (ty << 2) + i;
        size_t gir = (size_t)(n * 64 + t) * GI_N;   // x row for (seq n, step t) = n*64+t
        float i_r = gi[gir + unit];
        float i_z = gi[gir + HID + unit];
        float i_n = gi[gir + 2 * HID + unit];
        float hp  = hprev[(size_t)n * HID + unit];
        float r = sigmoidf_(i_r + acc0[i] + br);
        float z = sigmoidf_(i_z + acc1[i] + bz);
        float nn = tanhf(i_n + r * (acc2[i] + bn));
        hout[(size_t)n * HID + unit] = (1.0f - z) * nn + z * hp;
    }
}

// ======================= small-N GEMM: vl_preds = x @ cls_w^T + cls_b (N=21, K=2048) =========
__global__ __launch_bounds__(256) void vl_kernel(
    const float* __restrict__ A, const float* __restrict__ W,
    const float* __restrict__ bias, float* __restrict__ out)
{
    __shared__ float As[32][65];
    __shared__ float Ws[24][65];
    const int tid = threadIdx.x;
    const int r = tid >> 3;      // 0..31 row
    const int s = tid & 7;       // col group
    const int r0 = blockIdx.x * 32;
    float acc[3] = {0.f, 0.f, 0.f};

    for (int kc = 0; kc < FEAT; kc += 64) {
#pragma unroll
        for (int jj = 0; jj < 2; jj++) {
            int id = tid + jj * 256;           // 0..511
            int row = id >> 4;                  // 0..31
            int q = id & 15;
            float4 v = *(const float4*)(A + (size_t)(r0 + row) * FEAT + kc + q * 4);
            As[row][q*4+0] = v.x; As[row][q*4+1] = v.y;
            As[row][q*4+2] = v.z; As[row][q*4+3] = v.w;
        }
#pragma unroll
        for (int jj = 0; jj < 2; jj++) {
            int id = tid + jj * 256;
            if (id < 21 * 16) {
                int row = id >> 4;              // 0..20
                int q = id & 15;
                float4 v = *(const float4*)(W + (size_t)row * FEAT + kc + q * 4);
                Ws[row][q*4+0] = v.x; Ws[row][q*4+1] = v.y;
                Ws[row][q*4+2] = v.z; Ws[row][q*4+3] = v.w;
            }
        }
        __syncthreads();
#pragma unroll
        for (int kk = 0; kk < 64; kk++) {
            float a = As[r][kk];
#pragma unroll
            for (int cc = 0; cc < 3; cc++) {
                int c = s + 8 * cc;
                if (c < NCLS) acc[cc] += a * Ws[c][kk];
            }
        }
        __syncthreads();
    }
    int row = r0 + r;
#pragma unroll
    for (int cc = 0; cc < 3; cc++) {
        int c = s + 8 * cc;
        if (c < NCLS) out[(size_t)row * NCLS + c] = acc[cc] + bias[c];
    }
}

// ======================= final classifiers: [enc|mask] = relu(Hall) @ [cf;mk]^T + b ==========
__global__ __launch_bounds__(256) void cf_kernel(
    const float* __restrict__ Hrows,   // g_hall + NSEQ*HID (h_1..h_64)
    const float* __restrict__ cfw, const float* __restrict__ cfb,
    const float* __restrict__ mkw, const float* __restrict__ mkb,
    float* __restrict__ enc, float* __restrict__ mask)
{
    __shared__ float As[32][65];
    __shared__ float Ws[24][65];
    const int tid = threadIdx.x;
    const int r = tid >> 3;
    const int s = tid & 7;
    const int r0 = blockIdx.x * 32;
    float acc[3] = {0.f, 0.f, 0.f};

    for (int kc = 0; kc < HID; kc += 64) {
#pragma unroll
        for (int jj = 0; jj < 2; jj++) {
            int id = tid + jj * 256;
            int row = id >> 4;
            int q = id & 15;
            float4 v = *(const float4*)(Hrows + (size_t)(r0 + row) * HID + kc + q * 4);
            As[row][q*4+0] = fmaxf(v.x, 0.0f); As[row][q*4+1] = fmaxf(v.y, 0.0f);
            As[row][q*4+2] = fmaxf(v.z, 0.0f); As[row][q*4+3] = fmaxf(v.w, 0.0f);
        }
#pragma unroll
        for (int jj = 0; jj < 2; jj++) {
            int id = tid + jj * 256;
            if (id < 24 * 16) {
                int row = id >> 4;              // 0..23
                int q = id & 15;
                const float* src = (row < 22) ? (cfw + (size_t)row * HID)
                                              : (mkw + (size_t)(row - 22) * HID);
                float4 v = *(const float4*)(src + kc + q * 4);
                Ws[row][q*4+0] = v.x; Ws[row][q*4+1] = v.y;
                Ws[row][q*4+2] = v.z; Ws[row][q*4+3] = v.w;
            }
        }
        __syncthreads();
#pragma unroll
        for (int kk = 0; kk < 64; kk++) {
            float a = As[r][kk];
#pragma unroll
            for (int cc = 0; cc < 3; cc++) {
                int c = s + 8 * cc;               // 0..23, always valid
                acc[cc] += a * Ws[c][kk];
            }
        }
        __syncthreads();
    }
    int row = r0 + r;
#pragma unroll
    for (int cc = 0; cc < 3; cc++) {
        int c = s + 8 * cc;
        float b = (c < 22) ? cfb[c] : mkb[c - 22];
        float val = acc[cc] + b;
        if (c < 22) enc[(size_t)row * 22 + c] = val;
        else        mask[(size_t)row * 2 + (c - 22)] = val;
    }
}

// ======================= launch ==============================================================
extern "C" void kernel_launch(void* const* d_in, const int* in_sizes, int n_in,
                              void* d_out, int out_size)
{
    const float* feats = (const float*)d_in[0];
    const float* fc_w  = (const float*)d_in[1];
    const float* fc_b  = (const float*)d_in[2];
    const float* cls_w = (const float*)d_in[3];
    const float* cls_b = (const float*)d_in[4];
    const float* w_ih  = (const float*)d_in[5];
    const float* w_hh  = (const float*)d_in[6];
    const float* b_ih  = (const float*)d_in[7];
    const float* b_hh  = (const float*)d_in[8];
    const float* cf_w  = (const float*)d_in[9];
    const float* cf_b  = (const float*)d_in[10];
    const float* mk_w  = (const float*)d_in[11];
    const float* mk_b  = (const float*)d_in[12];

    float* out  = (float*)d_out;
    float* enc  = out;                        // [8192, 22]
    float* mask = out + 8192 * 22;            // [8192, 2]
    float* xbuf = out + 8192 * 22 + 8192 * 2; // [8192, 2048]
    float* vl   = xbuf + (size_t)ROWS * FEAT; // [8192, 21]

    float *gi_ptr = nullptr, *hall_ptr = nullptr;
    cudaGetSymbolAddress((void**)&gi_ptr, g_gi);
    cudaGetSymbolAddress((void**)&hall_ptr, g_hall);

    // 1. x = relu(feats @ fc_w^T + fc_b)
    sgemm_kernel<true><<<dim3(FEAT / 128, ROWS / 128), 256>>>(
        feats, fc_w, fc_b, xbuf, ROWS, FEAT, FEAT);

    // 2. dropout (JAX partitionable threefry XOR-fold, validated)
    dropout_kernel<<<(ROWS * FEAT) / (4 * 256), 256>>>(xbuf);

    // 3. vl_preds = x @ cls_w^T + cls_b
    vl_kernel<<<ROWS / 32, 256>>>(xbuf, cls_w, cls_b, vl);

    // 4. gi = x @ w_ih^T + b_ih   (all timesteps at once)
    sgemm_kernel<false><<<dim3(GI_N / 128, ROWS / 128), 256>>>(
        xbuf, w_ih, b_ih, gi_ptr, ROWS, GI_N, FEAT);

    // 5. h0 = 0
    cudaMemsetAsync(hall_ptr, 0, (size_t)NSEQ * HID * sizeof(float));

    // 6. sequential GRU scan
    for (int t = 0; t < NSTEP; t++) {
        gru_step_kernel<<<dim3(HID / 16, NSEQ / 64), 256>>>(gi_ptr, w_hh, b_hh, t);
    }

    // 7. enc/mask scores from relu(h_t) for all steps
    cf_kernel<<<ROWS / 32, 256>>>(hall_ptr + (size_t)NSEQ * HID,
                                  cf_w, cf_b, mk_w, mk_b, enc, mask);
}

// round 7
// speedup vs baseline: 1.4340x; 1.4340x over previous
#include <cuda_runtime.h>
#include <cuda_bf16.h>
#include <cstdint>

// Problem dims
#define ROWS   8192
#define FEAT   2048
#define HID    1024
#define GI_N   3072
#define NSEQ   128
#define NSTEP  64
#define NCLS   21

// ---------------- scratch ----------------
__device__ float g_gi[ROWS * GI_N];
__device__ float g_hall[(NSTEP + 1) * NSEQ * HID];
__device__ __nv_bfloat16 g_fh[ROWS * FEAT], g_fl[ROWS * FEAT];
__device__ __nv_bfloat16 g_xh[ROWS * FEAT], g_xl[ROWS * FEAT];
__device__ __nv_bfloat16 g_wfh[FEAT * FEAT], g_wfl[FEAT * FEAT];
__device__ __nv_bfloat16 g_wih[GI_N * FEAT], g_wil[GI_N * FEAT];

__device__ __forceinline__ float sigmoidf_(float x) { return 1.0f / (1.0f + expf(-x)); }

__device__ __forceinline__ uint32_t smem_u32(const void* p) {
    uint32_t a;
    asm("{ .reg .u64 t; cvta.to.shared.u64 t, %1; cvt.u32.u64 %0, t; }" : "=r"(a) : "l"(p));
    return a;
}
__device__ __forceinline__ void cp_async16(uint32_t dst, const void* src) {
    asm volatile("cp.async.cg.shared.global [%0], [%1], 16;" :: "r"(dst), "l"(src) : "memory");
}
__device__ __forceinline__ void ldmx4(uint32_t* r, uint32_t addr) {
    asm volatile("ldmatrix.sync.aligned.m8n8.x4.shared.b16 {%0,%1,%2,%3}, [%4];"
                 : "=r"(r[0]), "=r"(r[1]), "=r"(r[2]), "=r"(r[3]) : "r"(addr));
}
__device__ __forceinline__ void mma16816(float* c, const uint32_t* a, uint32_t b0, uint32_t b1) {
    asm volatile(
        "mma.sync.aligned.m16n8k16.row.col.f32.bf16.bf16.f32 "
        "{%0,%1,%2,%3}, {%4,%5,%6,%7}, {%8,%9}, {%0,%1,%2,%3};"
        : "+f"(c[0]), "+f"(c[1]), "+f"(c[2]), "+f"(c[3])
        : "r"(a[0]), "r"(a[1]), "r"(a[2]), "r"(a[3]), "r"(b0), "r"(b1));
}

// ---------------- threefry2x32 fold, key (0,42) ----------------
__device__ __forceinline__ unsigned int threefry_fold(unsigned int c1)
{
    const unsigned int ks1 = 42u;
    const unsigned int ks2 = 42u ^ 0x1BD11BDAu;
    unsigned int x0 = 0u;
    unsigned int x1 = c1 + ks1;
#define TFR(r) { x0 += x1; x1 = (x1 << (r)) | (x1 >> (32 - (r))); x1 ^= x0; }
    TFR(13) TFR(15) TFR(26) TFR(6)
    x0 += ks1; x1 += ks2 + 1u;
    TFR(17) TFR(29) TFR(16) TFR(24)
    x0 += ks2; x1 += 0u + 2u;
    TFR(13) TFR(15) TFR(26) TFR(6)
    x0 += 0u; x1 += ks1 + 3u;
    TFR(17) TFR(29) TFR(16) TFR(24)
    x0 += ks1; x1 += ks2 + 4u;
    TFR(13) TFR(15) TFR(26) TFR(6)
    x0 += ks2; x1 += 0u + 5u;
#undef TFR
    return x0 ^ x1;
}

// ---------------- fp32 -> bf16 hi/lo ----------------
__global__ __launch_bounds__(256) void convert_hilo(
    const float* __restrict__ in, __nv_bfloat16* __restrict__ hi,
    __nv_bfloat16* __restrict__ lo, int n)
{
    int i = (blockIdx.x * 256 + threadIdx.x) * 4;
    if (i >= n) return;
    float4 v = *(const float4*)(in + i);
    float vv[4] = {v.x, v.y, v.z, v.w};
    __nv_bfloat16 h[4], l[4];
#pragma unroll
    for (int e = 0; e < 4; e++) {
        h[e] = __float2bfloat16_rn(vv[e]);
        l[e] = __float2bfloat16_rn(vv[e] - __bfloat162float(h[e]));
    }
    *(__nv_bfloat162*)(hi + i)     = __nv_bfloat162(h[0], h[1]);
    *(__nv_bfloat162*)(hi + i + 2) = __nv_bfloat162(h[2], h[3]);
    *(__nv_bfloat162*)(lo + i)     = __nv_bfloat162(l[0], l[1]);
    *(__nv_bfloat162*)(lo + i + 2) = __nv_bfloat162(l[2], l[3]);
}

// =================== mma.sync split-bf16 GEMM ================================================
// C[M,N] = A[M,K] @ W[N,K]^T + bias via 3 bf16 passes. Block 128x128, 8 warps (32x64 tiles).
// K-chunk 64, double-buffered cp.async. MODE 0: fc epilogue (relu+dropout+x+xh/xl).
// MODE 1: gi epilogue (bias only).
#define LDAB  144                 // smem row pitch bytes (64 bf16 + 8 pad)
#define BUFB  (128 * LDAB)        // one operand buffer
#define STAGEB (4 * BUFB)         // Ah, Al, Wh, Wl
#define MM_SMEM (2 * STAGEB)      // double buffer = 147456 B

template<int MODE>
__global__ __launch_bounds__(256) void mma_gemm(
    const __nv_bfloat16* __restrict__ Ah, const __nv_bfloat16* __restrict__ Al,
    const __nv_bfloat16* __restrict__ Wh, const __nv_bfloat16* __restrict__ Wl,
    const float* __restrict__ bias, float* __restrict__ Cf,
    __nv_bfloat16* __restrict__ Ch, __nv_bfloat16* __restrict__ Cl,
    int K, int Nout)
{
    extern __shared__ char smem[];
    const uint32_t sb = smem_u32(smem);
    const int tid = threadIdx.x;
    const int wid = tid >> 5, lane = tid & 31;
    const int wm = wid & 3, wn = wid >> 2;
    const int g = lane >> 2, t = lane & 3;
    const int m0 = blockIdx.y * 128, n0 = blockIdx.x * 128;
    const size_t rowb = (size_t)K * 2;
    const char* srcp[4] = { (const char*)Ah + (size_t)m0 * rowb,
                            (const char*)Al + (size_t)m0 * rowb,
                            (const char*)Wh + (size_t)n0 * rowb,
                            (const char*)Wl + (size_t)n0 * rowb };
    const int nstages = K / 64;

    float c[2][8][4];
#pragma unroll
    for (int i = 0; i < 2; i++)
#pragma unroll
        for (int j = 0; j < 8; j++)
#pragma unroll
            for (int q = 0; q < 4; q++) c[i][j][q] = 0.0f;

    // ---- stage loader: 4096 x 16B chunks -> 16 per thread ----
    auto load_stage = [&](int s) {
        uint32_t dstb = sb + (uint32_t)(s & 1) * STAGEB;
        int kb = s * 128;   // byte offset along K
#pragma unroll
        for (int it = 0; it < 16; it++) {
            int id = tid + it * 256;
            int buf = id >> 10;
            int local = id & 1023;
            int row = local >> 3, cc = local & 7;
            cp_async16(dstb + buf * BUFB + row * LDAB + cc * 16,
                       srcp[buf] + (size_t)row * rowb + kb + cc * 16);
        }
        asm volatile("cp.async.commit_group;" ::: "memory");
    };

    load_stage(0);
    for (int s = 0; s < nstages; s++) {
        if (s + 1 < nstages) {
            load_stage(s + 1);
            asm volatile("cp.async.wait_group 1;" ::: "memory");
        } else {
            asm volatile("cp.async.wait_group 0;" ::: "memory");
        }
        __syncthreads();

        const uint32_t base = sb + (uint32_t)(s & 1) * STAGEB;
        const uint32_t aoff = base + (wm * 32 + (lane & 15)) * LDAB + (lane >> 4) * 16;
        const uint32_t woff = base + 2 * BUFB + (wn * 64 + (lane & 15)) * LDAB + (lane >> 4) * 16;

#pragma unroll
        for (int ks = 0; ks < 4; ks++) {
            const uint32_t kb2 = ks * 32;  // 16 k-elems = 32 B
            uint32_t ah[2][4], al[2][4], wh[4][4], wl[4][4];
            ldmx4(ah[0], aoff + kb2);
            ldmx4(ah[1], aoff + 16 * LDAB + kb2);
            ldmx4(al[0], aoff + BUFB + kb2);
            ldmx4(al[1], aoff + BUFB + 16 * LDAB + kb2);
#pragma unroll
            for (int p = 0; p < 4; p++) {
                ldmx4(wh[p], woff + p * 16 * LDAB + kb2);
                ldmx4(wl[p], woff + BUFB + p * 16 * LDAB + kb2);
            }
#pragma unroll
            for (int mt = 0; mt < 2; mt++)
#pragma unroll
                for (int nt = 0; nt < 8; nt++) {
                    uint32_t b0h = wh[nt >> 1][nt & 1], b1h = wh[nt >> 1][2 + (nt & 1)];
                    uint32_t b0l = wl[nt >> 1][nt & 1], b1l = wl[nt >> 1][2 + (nt & 1)];
                    mma16816(c[mt][nt], ah[mt], b0h, b1h);   // ah*wh
                    mma16816(c[mt][nt], ah[mt], b0l, b1l);   // ah*wl
                    mma16816(c[mt][nt], al[mt], b0h, b1h);   // al*wh
                }
        }
        __syncthreads();
    }

    // ---- epilogue ----
#pragma unroll
    for (int mt = 0; mt < 2; mt++)
#pragma unroll
        for (int nt = 0; nt < 8; nt++) {
            const int mrow = m0 + wm * 32 + mt * 16 + g;
            const int ncol = n0 + wn * 64 + nt * 8 + t * 2;
            const float b0 = bias[ncol], b1 = bias[ncol + 1];
#pragma unroll
            for (int half = 0; half < 2; half++) {
                const int m = mrow + half * 8;
                float v0 = c[mt][nt][half * 2 + 0] + b0;
                float v1 = c[mt][nt][half * 2 + 1] + b1;
                if (MODE == 0) {
                    v0 = fmaxf(v0, 0.0f); v1 = fmaxf(v1, 0.0f);
                    unsigned int i0 = (unsigned int)(m * 2048 + ncol);
                    unsigned int bt0 = threefry_fold(i0);
                    unsigned int bt1 = threefry_fold(i0 + 1);
                    float u0 = __uint_as_float((bt0 >> 9) | 0x3f800000u) - 1.0f;
                    float u1 = __uint_as_float((bt1 >> 9) | 0x3f800000u) - 1.0f;
                    v0 = (u0 < 0.7f) ? v0 * (1.0f / 0.7f) : 0.0f;
                    v1 = (u1 < 0.7f) ? v1 * (1.0f / 0.7f) : 0.0f;
                    *(float2*)(Cf + (size_t)m * 2048 + ncol) = make_float2(v0, v1);
                    __nv_bfloat16 h0 = __float2bfloat16_rn(v0);
                    __nv_bfloat16 h1 = __float2bfloat16_rn(v1);
                    *(__nv_bfloat162*)(Ch + (size_t)m * 2048 + ncol) = __nv_bfloat162(h0, h1);
                    *(__nv_bfloat162*)(Cl + (size_t)m * 2048 + ncol) = __nv_bfloat162(
                        __float2bfloat16_rn(v0 - __bfloat162float(h0)),
                        __float2bfloat16_rn(v1 - __bfloat162float(h1)));
                } else {
                    *(float2*)(Cf + (size_t)m * Nout + ncol) = make_float2(v0, v1);
                }
            }
        }
}

// ======================= GRU step (unchanged, validated) ======================================
__global__ __launch_bounds__(256) void gru_step_kernel(
    const float* __restrict__ gi, const float* __restrict__ whh,
    const float* __restrict__ bhh, int t)
{
    __shared__ float hs[32][65];
    __shared__ float ws[48][33];
    const int tid = threadIdx.x;
    const int tx = tid & 15;
    const int ty = tid >> 4;
    const int u0 = blockIdx.x * 16;
    const int m0 = blockIdx.y * 64;

    const float* hprev = g_hall + (size_t)t * NSEQ * HID;
    float* hout        = g_hall + (size_t)(t + 1) * NSEQ * HID;

    float acc0[4] = {0.f,0.f,0.f,0.f};
    float acc1[4] = {0.f,0.f,0.f,0.f};
    float acc2[4] = {0.f,0.f,0.f,0.f};

    for (int kc = 0; kc < HID; kc += 32) {
#pragma unroll
        for (int jj = 0; jj < 2; jj++) {
            int id = tid + jj * 256;
            int row = id >> 3, q = id & 7;
            float4 v = *(const float4*)(hprev + (size_t)(m0 + row) * HID + kc + q * 4);
            hs[q*4+0][row] = v.x; hs[q*4+1][row] = v.y;
            hs[q*4+2][row] = v.z; hs[q*4+3][row] = v.w;
        }
#pragma unroll
        for (int jj = 0; jj < 2; jj++) {
            int id = tid + jj * 256;
            if (id < 384) {
                int gcol = id >> 3, q = id & 7;
                int grow = (gcol >> 4) * HID + u0 + (gcol & 15);
                float4 v = *(const float4*)(whh + (size_t)grow * HID + kc + q * 4);
                ws[gcol][q*4+0] = v.x; ws[gcol][q*4+1] = v.y;
                ws[gcol][q*4+2] = v.z; ws[gcol][q*4+3] = v.w;
            }
        }
        __syncthreads();
#pragma unroll
        for (int kk = 0; kk < 32; kk++) {
            float w0 = ws[tx][kk], w1 = ws[16 + tx][kk], w2 = ws[32 + tx][kk];
#pragma unroll
            for (int i = 0; i < 4; i++) {
                float h = hs[kk][(ty << 2) + i];
                acc0[i] += w0 * h; acc1[i] += w1 * h; acc2[i] += w2 * h;
            }
        }
        __syncthreads();
    }

    const int unit = u0 + tx;
    const float br = bhh[unit], bz = bhh[HID + unit], bn = bhh[2 * HID + unit];
#pragma unroll
    for (int i = 0; i < 4; i++) {
        int n = m0 + (ty << 2) + i;
        size_t gir = (size_t)(n * 64 + t) * GI_N;
        float i_r = gi[gir + unit];
        float i_z = gi[gir + HID + unit];
        float i_n = gi[gir + 2 * HID + unit];
        float hp  = hprev[(size_t)n * HID + unit];
        float r = sigmoidf_(i_r + acc0[i] + br);
        float z = sigmoidf_(i_z + acc1[i] + bz);
        float nn = tanhf(i_n + r * (acc2[i] + bn));
        hout[(size_t)n * HID + unit] = (1.0f - z) * nn + z * hp;
    }
}

// ======================= vl & cf small-N GEMMs (unchanged, validated) =========================
__global__ __launch_bounds__(256) void vl_kernel(
    const float* __restrict__ A, const float* __restrict__ W,
    const float* __restrict__ bias, float* __restrict__ out)
{
    __shared__ float As[32][65];
    __shared__ float Ws[24][65];
    const int tid = threadIdx.x;
    const int r = tid >> 3, s = tid & 7;
    const int r0 = blockIdx.x * 32;
    float acc[3] = {0.f, 0.f, 0.f};

    for (int kc = 0; kc < FEAT; kc += 64) {
#pragma unroll
        for (int jj = 0; jj < 2; jj++) {
            int id = tid + jj * 256;
            int row = id >> 4, q = id & 15;
            float4 v = *(const float4*)(A + (size_t)(r0 + row) * FEAT + kc + q * 4);
            As[row][q*4+0] = v.x; As[row][q*4+1] = v.y;
            As[row][q*4+2] = v.z; As[row][q*4+3] = v.w;
        }
#pragma unroll
        for (int jj = 0; jj < 2; jj++) {
            int id = tid + jj * 256;
            if (id < 21 * 16) {
                int row = id >> 4, q = id & 15;
                float4 v = *(const float4*)(W + (size_t)row * FEAT + kc + q * 4);
                Ws[row][q*4+0] = v.x; Ws[row][q*4+1] = v.y;
                Ws[row][q*4+2] = v.z; Ws[row][q*4+3] = v.w;
            }
        }
        __syncthreads();
#pragma unroll
        for (int kk = 0; kk < 64; kk++) {
            float a = As[r][kk];
#pragma unroll
            for (int cc = 0; cc < 3; cc++) {
                int c = s + 8 * cc;
                if (c < NCLS) acc[cc] += a * Ws[c][kk];
            }
        }
        __syncthreads();
    }
    int row = r0 + r;
#pragma unroll
    for (int cc = 0; cc < 3; cc++) {
        int c = s + 8 * cc;
        if (c < NCLS) out[(size_t)row * NCLS + c] = acc[cc] + bias[c];
    }
}

__global__ __launch_bounds__(256) void cf_kernel(
    const float* __restrict__ Hrows,
    const float* __restrict__ cfw, const float* __restrict__ cfb,
    const float* __restrict__ mkw, const float* __restrict__ mkb,
    float* __restrict__ enc, float* __restrict__ mask)
{
    __shared__ float As[32][65];
    __shared__ float Ws[24][65];
    const int tid = threadIdx.x;
    const int r = tid >> 3, s = tid & 7;
    const int r0 = blockIdx.x * 32;
    float acc[3] = {0.f, 0.f, 0.f};

    for (int kc = 0; kc < HID; kc += 64) {
#pragma unroll
        for (int jj = 0; jj < 2; jj++) {
            int id = tid + jj * 256;
            int row = id >> 4, q = id & 15;
            float4 v = *(const float4*)(Hrows + (size_t)(r0 + row) * HID + kc + q * 4);
            As[row][q*4+0] = fmaxf(v.x, 0.0f); As[row][q*4+1] = fmaxf(v.y, 0.0f);
            As[row][q*4+2] = fmaxf(v.z, 0.0f); As[row][q*4+3] = fmaxf(v.w, 0.0f);
        }
#pragma unroll
        for (int jj = 0; jj < 2; jj++) {
            int id = tid + jj * 256;
            if (id < 24 * 16) {
                int row = id >> 4, q = id & 15;
                const float* src = (row < 22) ? (cfw + (size_t)row * HID)
                                              : (mkw + (size_t)(row - 22) * HID);
                float4 v = *(const float4*)(src + kc + q * 4);
                Ws[row][q*4+0] = v.x; Ws[row][q*4+1] = v.y;
                Ws[row][q*4+2] = v.z; Ws[row][q*4+3] = v.w;
            }
        }
        __syncthreads();
#pragma unroll
        for (int kk = 0; kk < 64; kk++) {
            float a = As[r][kk];
#pragma unroll
            for (int cc = 0; cc < 3; cc++) {
                int c = s + 8 * cc;
                acc[cc] += a * Ws[c][kk];
            }
        }
        __syncthreads();
    }
    int row = r0 + r;
#pragma unroll
    for (int cc = 0; cc < 3; cc++) {
        int c = s + 8 * cc;
        float b = (c < 22) ? cfb[c] : mkb[c - 22];
        float val = acc[cc] + b;
        if (c < 22) enc[(size_t)row * 22 + c] = val;
        else        mask[(size_t)row * 2 + (c - 22)] = val;
    }
}

// ======================= launch ==============================================================
extern "C" void kernel_launch(void* const* d_in, const int* in_sizes, int n_in,
                              void* d_out, int out_size)
{
    const float* feats = (const float*)d_in[0];
    const float* fc_w  = (const float*)d_in[1];
    const float* fc_b  = (const float*)d_in[2];
    const float* cls_w = (const float*)d_in[3];
    const float* cls_b = (const float*)d_in[4];
    const float* w_ih  = (const float*)d_in[5];
    const float* w_hh  = (const float*)d_in[6];
    const float* b_ih  = (const float*)d_in[7];
    const float* b_hh  = (const float*)d_in[8];
    const float* cf_w  = (const float*)d_in[9];
    const float* cf_b  = (const float*)d_in[10];
    const float* mk_w  = (const float*)d_in[11];
    const float* mk_b  = (const float*)d_in[12];

    float* out  = (float*)d_out;
    float* enc  = out;
    float* mask = out + 8192 * 22;
    float* xbuf = out + 8192 * 22 + 8192 * 2;
    float* vl   = xbuf + (size_t)ROWS * FEAT;

    float *gi_ptr, *hall_ptr;
    __nv_bfloat16 *fh, *fl, *xh, *xl, *wfh, *wfl, *wihh, *wihl;
    cudaGetSymbolAddress((void**)&gi_ptr, g_gi);
    cudaGetSymbolAddress((void**)&hall_ptr, g_hall);
    cudaGetSymbolAddress((void**)&fh, g_fh);   cudaGetSymbolAddress((void**)&fl, g_fl);
    cudaGetSymbolAddress((void**)&xh, g_xh);   cudaGetSymbolAddress((void**)&xl, g_xl);
    cudaGetSymbolAddress((void**)&wfh, g_wfh); cudaGetSymbolAddress((void**)&wfl, g_wfl);
    cudaGetSymbolAddress((void**)&wihh, g_wih); cudaGetSymbolAddress((void**)&wihl, g_wil);

    cudaFuncSetAttribute(mma_gemm<0>, cudaFuncAttributeMaxDynamicSharedMemorySize, MM_SMEM);
    cudaFuncSetAttribute(mma_gemm<1>, cudaFuncAttributeMaxDynamicSharedMemorySize, MM_SMEM);

    // 0. fp32 -> bf16 hi/lo converts
    convert_hilo<<<(ROWS * FEAT) / 1024, 256>>>(feats, fh, fl, ROWS * FEAT);
    convert_hilo<<<(FEAT * FEAT) / 1024, 256>>>(fc_w, wfh, wfl, FEAT * FEAT);
    convert_hilo<<<(GI_N * FEAT) / 1024, 256>>>(w_ih, wihh, wihl, GI_N * FEAT);

    // 1. fc GEMM (HMMA) + fused bias/relu/dropout + x fp32 + x bf16 hi/lo
    mma_gemm<0><<<dim3(FEAT / 128, ROWS / 128), 256, MM_SMEM>>>(
        fh, fl, wfh, wfl, fc_b, xbuf, xh, xl, FEAT, FEAT);

    // 2. vl_preds = x @ cls_w^T + cls_b
    vl_kernel<<<ROWS / 32, 256>>>(xbuf, cls_w, cls_b, vl);

    // 3. gi = x @ w_ih^T + b_ih (HMMA)
    mma_gemm<1><<<dim3(GI_N / 128, ROWS / 128), 256, MM_SMEM>>>(
        xh, xl, wihh, wihl, b_ih, gi_ptr, nullptr, nullptr, FEAT, GI_N);

    // 4. h0 = 0
    cudaMemsetAsync(hall_ptr, 0, (size_t)NSEQ * HID * sizeof(float));

    // 5. sequential GRU scan
    for (int t = 0; t < NSTEP; t++)
        gru_step_kernel<<<dim3(HID / 16, NSEQ / 64), 256>>>(gi_ptr, w_hh, b_hh, t);

    // 6. enc/mask scores
    cf_kernel<<<ROWS / 32, 256>>>(hall_ptr + (size_t)NSEQ * HID,
                                  cf_w, cf_b, mk_w, mk_b, enc, mask);
}

// round 8
// speedup vs baseline: 2.0365x; 1.4201x over previous
#include <cuda_runtime.h>
#include <cuda_bf16.h>
#include <cstdint>

// Problem dims
#define ROWS   8192
#define FEAT   2048
#define HID    1024
#define GI_N   3072
#define NSEQ   128
#define NSTEP  64
#define NCLS   21

// ---------------- scratch ----------------
__device__ float g_gi[ROWS * GI_N];
__device__ float g_hall[(NSTEP + 1) * NSEQ * HID];
__device__ float g_gh[NSEQ * GI_N];                              // per-step gh
__device__ __nv_bfloat16 g_fh[ROWS * FEAT], g_fl[ROWS * FEAT];
__device__ __nv_bfloat16 g_xh[ROWS * FEAT], g_xl[ROWS * FEAT];
__device__ __nv_bfloat16 g_wfh[FEAT * FEAT], g_wfl[FEAT * FEAT];
__device__ __nv_bfloat16 g_wih[GI_N * FEAT], g_wil[GI_N * FEAT];
__device__ __nv_bfloat16 g_whh[GI_N * HID], g_whl[GI_N * HID];   // w_hh hi/lo
__device__ __nv_bfloat16 g_hbh[2 * NSEQ * HID], g_hbl[2 * NSEQ * HID]; // h ping-pong hi/lo

__device__ __forceinline__ float sigmoidf_(float x) { return 1.0f / (1.0f + expf(-x)); }

__device__ __forceinline__ uint32_t smem_u32(const void* p) {
    uint32_t a;
    asm("{ .reg .u64 t; cvta.to.shared.u64 t, %1; cvt.u32.u64 %0, t; }" : "=r"(a) : "l"(p));
    return a;
}
__device__ __forceinline__ void cp_async16(uint32_t dst, const void* src) {
    asm volatile("cp.async.cg.shared.global [%0], [%1], 16;" :: "r"(dst), "l"(src) : "memory");
}
__device__ __forceinline__ void ldmx4(uint32_t* r, uint32_t addr) {
    asm volatile("ldmatrix.sync.aligned.m8n8.x4.shared.b16 {%0,%1,%2,%3}, [%4];"
                 : "=r"(r[0]), "=r"(r[1]), "=r"(r[2]), "=r"(r[3]) : "r"(addr));
}
__device__ __forceinline__ void mma16816(float* c, const uint32_t* a, uint32_t b0, uint32_t b1) {
    asm volatile(
        "mma.sync.aligned.m16n8k16.row.col.f32.bf16.bf16.f32 "
        "{%0,%1,%2,%3}, {%4,%5,%6,%7}, {%8,%9}, {%0,%1,%2,%3};"
        : "+f"(c[0]), "+f"(c[1]), "+f"(c[2]), "+f"(c[3])
        : "r"(a[0]), "r"(a[1]), "r"(a[2]), "r"(a[3]), "r"(b0), "r"(b1));
}

// ---------------- threefry2x32 fold, key (0,42) ----------------
__device__ __forceinline__ unsigned int threefry_fold(unsigned int c1)
{
    const unsigned int ks1 = 42u;
    const unsigned int ks2 = 42u ^ 0x1BD11BDAu;
    unsigned int x0 = 0u;
    unsigned int x1 = c1 + ks1;
#define TFR(r) { x0 += x1; x1 = (x1 << (r)) | (x1 >> (32 - (r))); x1 ^= x0; }
    TFR(13) TFR(15) TFR(26) TFR(6)
    x0 += ks1; x1 += ks2 + 1u;
    TFR(17) TFR(29) TFR(16) TFR(24)
    x0 += ks2; x1 += 0u + 2u;
    TFR(13) TFR(15) TFR(26) TFR(6)
    x0 += 0u; x1 += ks1 + 3u;
    TFR(17) TFR(29) TFR(16) TFR(24)
    x0 += ks1; x1 += ks2 + 4u;
    TFR(13) TFR(15) TFR(26) TFR(6)
    x0 += ks2; x1 += 0u + 5u;
#undef TFR
    return x0 ^ x1;
}

// ---------------- fp32 -> bf16 hi/lo ----------------
__global__ __launch_bounds__(256) void convert_hilo(
    const float* __restrict__ in, __nv_bfloat16* __restrict__ hi,
    __nv_bfloat16* __restrict__ lo, int n)
{
    int i = (blockIdx.x * 256 + threadIdx.x) * 4;
    if (i >= n) return;
    float4 v = *(const float4*)(in + i);
    float vv[4] = {v.x, v.y, v.z, v.w};
    __nv_bfloat16 h[4], l[4];
#pragma unroll
    for (int e = 0; e < 4; e++) {
        h[e] = __float2bfloat16_rn(vv[e]);
        l[e] = __float2bfloat16_rn(vv[e] - __bfloat162float(h[e]));
    }
    *(__nv_bfloat162*)(hi + i)     = __nv_bfloat162(h[0], h[1]);
    *(__nv_bfloat162*)(hi + i + 2) = __nv_bfloat162(h[2], h[3]);
    *(__nv_bfloat162*)(lo + i)     = __nv_bfloat162(l[0], l[1]);
    *(__nv_bfloat162*)(lo + i + 2) = __nv_bfloat162(l[2], l[3]);
}

// =================== big mma.sync split-bf16 GEMM (unchanged from R7, validated) =============
#define LDAB  144
#define BUFB  (128 * LDAB)
#define STAGEB (4 * BUFB)
#define MM_SMEM (2 * STAGEB)

template<int MODE>
__global__ __launch_bounds__(256) void mma_gemm(
    const __nv_bfloat16* __restrict__ Ah, const __nv_bfloat16* __restrict__ Al,
    const __nv_bfloat16* __restrict__ Wh, const __nv_bfloat16* __restrict__ Wl,
    const float* __restrict__ bias, float* __restrict__ Cf,
    __nv_bfloat16* __restrict__ Ch, __nv_bfloat16* __restrict__ Cl,
    int K, int Nout)
{
    extern __shared__ char smem[];
    const uint32_t sb = smem_u32(smem);
    const int tid = threadIdx.x;
    const int wid = tid >> 5, lane = tid & 31;
    const int wm = wid & 3, wn = wid >> 2;
    const int g = lane >> 2, t = lane & 3;
    const int m0 = blockIdx.y * 128, n0 = blockIdx.x * 128;
    const size_t rowb = (size_t)K * 2;
    const char* srcp[4] = { (const char*)Ah + (size_t)m0 * rowb,
                            (const char*)Al + (size_t)m0 * rowb,
                            (const char*)Wh + (size_t)n0 * rowb,
                            (const char*)Wl + (size_t)n0 * rowb };
    const int nstages = K / 64;

    float c[2][8][4];
#pragma unroll
    for (int i = 0; i < 2; i++)
#pragma unroll
        for (int j = 0; j < 8; j++)
#pragma unroll
            for (int q = 0; q < 4; q++) c[i][j][q] = 0.0f;

    auto load_stage = [&](int s) {
        uint32_t dstb = sb + (uint32_t)(s & 1) * STAGEB;
        int kb = s * 128;
#pragma unroll
        for (int it = 0; it < 16; it++) {
            int id = tid + it * 256;
            int buf = id >> 10;
            int local = id & 1023;
            int row = local >> 3, cc = local & 7;
            cp_async16(dstb + buf * BUFB + row * LDAB + cc * 16,
                       srcp[buf] + (size_t)row * rowb + kb + cc * 16);
        }
        asm volatile("cp.async.commit_group;" ::: "memory");
    };

    load_stage(0);
    for (int s = 0; s < nstages; s++) {
        if (s + 1 < nstages) {
            load_stage(s + 1);
            asm volatile("cp.async.wait_group 1;" ::: "memory");
        } else {
            asm volatile("cp.async.wait_group 0;" ::: "memory");
        }
        __syncthreads();

        const uint32_t base = sb + (uint32_t)(s & 1) * STAGEB;
        const uint32_t aoff = base + (wm * 32 + (lane & 15)) * LDAB + (lane >> 4) * 16;
        const uint32_t woff = base + 2 * BUFB + (wn * 64 + (lane & 15)) * LDAB + (lane >> 4) * 16;

#pragma unroll
        for (int ks = 0; ks < 4; ks++) {
            const uint32_t kb2 = ks * 32;
            uint32_t ah[2][4], al[2][4], wh[4][4], wl[4][4];
            ldmx4(ah[0], aoff + kb2);
            ldmx4(ah[1], aoff + 16 * LDAB + kb2);
            ldmx4(al[0], aoff + BUFB + kb2);
            ldmx4(al[1], aoff + BUFB + 16 * LDAB + kb2);
#pragma unroll
            for (int p = 0; p < 4; p++) {
                ldmx4(wh[p], woff + p * 16 * LDAB + kb2);
                ldmx4(wl[p], woff + BUFB + p * 16 * LDAB + kb2);
            }
#pragma unroll
            for (int mt = 0; mt < 2; mt++)
#pragma unroll
                for (int nt = 0; nt < 8; nt++) {
                    uint32_t b0h = wh[nt >> 1][nt & 1], b1h = wh[nt >> 1][2 + (nt & 1)];
                    uint32_t b0l = wl[nt >> 1][nt & 1], b1l = wl[nt >> 1][2 + (nt & 1)];
                    mma16816(c[mt][nt], ah[mt], b0h, b1h);
                    mma16816(c[mt][nt], ah[mt], b0l, b1l);
                    mma16816(c[mt][nt], al[mt], b0h, b1h);
                }
        }
        __syncthreads();
    }

#pragma unroll
    for (int mt = 0; mt < 2; mt++)
#pragma unroll
        for (int nt = 0; nt < 8; nt++) {
            const int mrow = m0 + wm * 32 + mt * 16 + g;
            const int ncol = n0 + wn * 64 + nt * 8 + t * 2;
            const float b0 = bias[ncol], b1 = bias[ncol + 1];
#pragma unroll
            for (int half = 0; half < 2; half++) {
                const int m = mrow + half * 8;
                float v0 = c[mt][nt][half * 2 + 0] + b0;
                float v1 = c[mt][nt][half * 2 + 1] + b1;
                if (MODE == 0) {
                    v0 = fmaxf(v0, 0.0f); v1 = fmaxf(v1, 0.0f);
                    unsigned int i0 = (unsigned int)(m * 2048 + ncol);
                    unsigned int bt0 = threefry_fold(i0);
                    unsigned int bt1 = threefry_fold(i0 + 1);
                    float u0 = __uint_as_float((bt0 >> 9) | 0x3f800000u) - 1.0f;
                    float u1 = __uint_as_float((bt1 >> 9) | 0x3f800000u) - 1.0f;
                    v0 = (u0 < 0.7f) ? v0 * (1.0f / 0.7f) : 0.0f;
                    v1 = (u1 < 0.7f) ? v1 * (1.0f / 0.7f) : 0.0f;
                    *(float2*)(Cf + (size_t)m * 2048 + ncol) = make_float2(v0, v1);
                    __nv_bfloat16 h0 = __float2bfloat16_rn(v0);
                    __nv_bfloat16 h1 = __float2bfloat16_rn(v1);
                    *(__nv_bfloat162*)(Ch + (size_t)m * 2048 + ncol) = __nv_bfloat162(h0, h1);
                    *(__nv_bfloat162*)(Cl + (size_t)m * 2048 + ncol) = __nv_bfloat162(
                        __float2bfloat16_rn(v0 - __bfloat162float(h0)),
                        __float2bfloat16_rn(v1 - __bfloat162float(h1)));
                } else {
                    *(float2*)(Cf + (size_t)m * Nout + ncol) = make_float2(v0, v1);
                }
            }
        }
}

// =================== GRU gh GEMM: gh[128,3072] = h[128,1024] @ w_hh^T (HMMA 3-pass) ==========
// Tile 64(M) x 64(N), grid (48, 2) = 96 CTAs. K=1024, 16 stages of 64.
#define GBUF   (64 * LDAB)        // 9216
#define GSTAGE (4 * GBUF)         // 36864
#define GH_SMEM (2 * GSTAGE)      // 73728

__global__ __launch_bounds__(256) void gh_gemm(
    const __nv_bfloat16* __restrict__ Hh, const __nv_bfloat16* __restrict__ Hl,
    const __nv_bfloat16* __restrict__ Wh, const __nv_bfloat16* __restrict__ Wl,
    float* __restrict__ gh)
{
    extern __shared__ char smem[];
    const uint32_t sb = smem_u32(smem);
    const int tid = threadIdx.x;
    const int wid = tid >> 5, lane = tid & 31;
    const int wm = wid & 1, wn = wid >> 1;        // 2 x 4 warps -> 32x16 warp tile
    const int g = lane >> 2, t = lane & 3;
    const int n0 = blockIdx.x * 64, m0 = blockIdx.y * 64;
    const char* srcp[4] = { (const char*)(Hh + (size_t)m0 * HID),
                            (const char*)(Hl + (size_t)m0 * HID),
                            (const char*)(Wh + (size_t)n0 * HID),
                            (const char*)(Wl + (size_t)n0 * HID) };

    float c[2][2][4];
#pragma unroll
    for (int i = 0; i < 2; i++)
#pragma unroll
        for (int j = 0; j < 2; j++)
#pragma unroll
            for (int q = 0; q < 4; q++) c[i][j][q] = 0.0f;

    auto load_stage = [&](int s) {
        uint32_t dstb = sb + (uint32_t)(s & 1) * GSTAGE;
        int kb = s * 128;
#pragma unroll
        for (int it = 0; it < 8; it++) {
            int id = tid + it * 256;
            int buf = id >> 9, local = id & 511;
            int row = local >> 3, cc = local & 7;
            cp_async16(dstb + buf * GBUF + row * LDAB + cc * 16,
                       srcp[buf] + (size_t)row * 2048 + kb + cc * 16);
        }
        asm volatile("cp.async.commit_group;" ::: "memory");
    };

    load_stage(0);
    for (int s = 0; s < 16; s++) {
        if (s + 1 < 16) {
            load_stage(s + 1);
            asm volatile("cp.async.wait_group 1;" ::: "memory");
        } else {
            asm volatile("cp.async.wait_group 0;" ::: "memory");
        }
        __syncthreads();

        const uint32_t base = sb + (uint32_t)(s & 1) * GSTAGE;
        const uint32_t aoff = base + (wm * 32 + (lane & 15)) * LDAB + (lane >> 4) * 16;
        const uint32_t woff = base + 2 * GBUF + (wn * 16 + (lane & 15)) * LDAB + (lane >> 4) * 16;

#pragma unroll
        for (int ks = 0; ks < 4; ks++) {
            const uint32_t kb2 = ks * 32;
            uint32_t ah[2][4], al[2][4], wh[4], wl[4];
            ldmx4(ah[0], aoff + kb2);
            ldmx4(ah[1], aoff + 16 * LDAB + kb2);
            ldmx4(al[0], aoff + GBUF + kb2);
            ldmx4(al[1], aoff + GBUF + 16 * LDAB + kb2);
            ldmx4(wh, woff + kb2);
            ldmx4(wl, woff + GBUF + kb2);
#pragma unroll
            for (int mt = 0; mt < 2; mt++)
#pragma unroll
                for (int nt = 0; nt < 2; nt++) {
                    uint32_t b0h = wh[nt], b1h = wh[2 + nt];
                    uint32_t b0l = wl[nt], b1l = wl[2 + nt];
                    mma16816(c[mt][nt], ah[mt], b0h, b1h);
                    mma16816(c[mt][nt], ah[mt], b0l, b1l);
                    mma16816(c[mt][nt], al[mt], b0h, b1h);
                }
        }
        __syncthreads();
    }

#pragma unroll
    for (int mt = 0; mt < 2; mt++)
#pragma unroll
        for (int nt = 0; nt < 2; nt++) {
            const int mrow = m0 + wm * 32 + mt * 16 + g;
            const int ncol = n0 + wn * 16 + nt * 8 + t * 2;
#pragma unroll
            for (int half = 0; half < 2; half++) {
                const int m = mrow + half * 8;
                *(float2*)(gh + (size_t)m * GI_N + ncol) =
                    make_float2(c[mt][nt][half * 2], c[mt][nt][half * 2 + 1]);
            }
        }
}

// =================== GRU gates (elementwise): h_{t+1} + bf16 hi/lo ping-pong ================
__global__ __launch_bounds__(256) void gate_kernel(
    const float* __restrict__ gi, const float* __restrict__ gh,
    const float* __restrict__ bhh, int t,
    __nv_bfloat16* __restrict__ Hh, __nv_bfloat16* __restrict__ Hl)
{
    const int n = blockIdx.x;            // sequence row 0..127
    const int u = threadIdx.x * 4;       // unit
    const float* hprev = g_hall + (size_t)t * NSEQ * HID;
    float* hout        = g_hall + (size_t)(t + 1) * NSEQ * HID;
    const size_t gib = (size_t)(n * 64 + t) * GI_N;
    const size_t ghb = (size_t)n * GI_N;

    float4 ir = *(const float4*)(gi + gib + u);
    float4 iz = *(const float4*)(gi + gib + HID + u);
    float4 inn = *(const float4*)(gi + gib + 2 * HID + u);
    float4 hr = *(const float4*)(gh + ghb + u);
    float4 hz = *(const float4*)(gh + ghb + HID + u);
    float4 hn = *(const float4*)(gh + ghb + 2 * HID + u);
    float4 br = *(const float4*)(bhh + u);
    float4 bz = *(const float4*)(bhh + HID + u);
    float4 bn = *(const float4*)(bhh + 2 * HID + u);
    float4 hp = *(const float4*)(hprev + (size_t)n * HID + u);

    float irv[4] = {ir.x, ir.y, ir.z, ir.w};
    float izv[4] = {iz.x, iz.y, iz.z, iz.w};
    float inv[4] = {inn.x, inn.y, inn.z, inn.w};
    float hrv[4] = {hr.x + br.x, hr.y + br.y, hr.z + br.z, hr.w + br.w};
    float hzv[4] = {hz.x + bz.x, hz.y + bz.y, hz.z + bz.z, hz.w + bz.w};
    float hnv[4] = {hn.x + bn.x, hn.y + bn.y, hn.z + bn.z, hn.w + bn.w};
    float hpv[4] = {hp.x, hp.y, hp.z, hp.w};
    float h[4];
#pragma unroll
    for (int e = 0; e < 4; e++) {
        float r = sigmoidf_(irv[e] + hrv[e]);
        float z = sigmoidf_(izv[e] + hzv[e]);
        float nn = tanhf(inv[e] + r * hnv[e]);
        h[e] = (1.0f - z) * nn + z * hpv[e];
    }
    *(float4*)(hout + (size_t)n * HID + u) = make_float4(h[0], h[1], h[2], h[3]);

    __nv_bfloat16 b0 = __float2bfloat16_rn(h[0]), b1 = __float2bfloat16_rn(h[1]);
    __nv_bfloat16 b2 = __float2bfloat16_rn(h[2]), b3 = __float2bfloat16_rn(h[3]);
    *(__nv_bfloat162*)(Hh + (size_t)n * HID + u)     = __nv_bfloat162(b0, b1);
    *(__nv_bfloat162*)(Hh + (size_t)n * HID + u + 2) = __nv_bfloat162(b2, b3);
    *(__nv_bfloat162*)(Hl + (size_t)n * HID + u) = __nv_bfloat162(
        __float2bfloat16_rn(h[0] - __bfloat162float(b0)),
        __float2bfloat16_rn(h[1] - __bfloat162float(b1)));
    *(__nv_bfloat162*)(Hl + (size_t)n * HID + u + 2) = __nv_bfloat162(
        __float2bfloat16_rn(h[2] - __bfloat162float(b2)),
        __float2bfloat16_rn(h[3] - __bfloat162float(b3)));
}

// ======================= vl & cf small-N GEMMs (unchanged, validated) =========================
__global__ __launch_bounds__(256) void vl_kernel(
    const float* __restrict__ A, const float* __restrict__ W,
    const float* __restrict__ bias, float* __restrict__ out)
{
    __shared__ float As[32][65];
    __shared__ float Ws[24][65];
    const int tid = threadIdx.x;
    const int r = tid >> 3, s = tid & 7;
    const int r0 = blockIdx.x * 32;
    float acc[3] = {0.f, 0.f, 0.f};

    for (int kc = 0; kc < FEAT; kc += 64) {
#pragma unroll
        for (int jj = 0; jj < 2; jj++) {
            int id = tid + jj * 256;
            int row = id >> 4, q = id & 15;
            float4 v = *(const float4*)(A + (size_t)(r0 + row) * FEAT + kc + q * 4);
            As[row][q*4+0] = v.x; As[row][q*4+1] = v.y;
            As[row][q*4+2] = v.z; As[row][q*4+3] = v.w;
        }
#pragma unroll
        for (int jj = 0; jj < 2; jj++) {
            int id = tid + jj * 256;
            if (id < 21 * 16) {
                int row = id >> 4, q = id & 15;
                float4 v = *(const float4*)(W + (size_t)row * FEAT + kc + q * 4);
                Ws[row][q*4+0] = v.x; Ws[row][q*4+1] = v.y;
                Ws[row][q*4+2] = v.z; Ws[row][q*4+3] = v.w;
            }
        }
        __syncthreads();
#pragma unroll
        for (int kk = 0; kk < 64; kk++) {
            float a = As[r][kk];
#pragma unroll
            for (int cc = 0; cc < 3; cc++) {
                int c = s + 8 * cc;
                if (c < NCLS) acc[cc] += a * Ws[c][kk];
            }
        }
        __syncthreads();
    }
    int row = r0 + r;
#pragma unroll
    for (int cc = 0; cc < 3; cc++) {
        int c = s + 8 * cc;
        if (c < NCLS) out[(size_t)row * NCLS + c] = acc[cc] + bias[c];
    }
}

__global__ __launch_bounds__(256) void cf_kernel(
    const float* __restrict__ Hrows,
    const float* __restrict__ cfw, const float* __restrict__ cfb,
    const float* __restrict__ mkw, const float* __restrict__ mkb,
    float* __restrict__ enc, float* __restrict__ mask)
{
    __shared__ float As[32][65];
    __shared__ float Ws[24][65];
    const int tid = threadIdx.x;
    const int r = tid >> 3, s = tid & 7;
    const int r0 = blockIdx.x * 32;
    float acc[3] = {0.f, 0.f, 0.f};

    for (int kc = 0; kc < HID; kc += 64) {
#pragma unroll
        for (int jj = 0; jj < 2; jj++) {
            int id = tid + jj * 256;
            int row = id >> 4, q = id & 15;
            float4 v = *(const float4*)(Hrows + (size_t)(r0 + row) * HID + kc + q * 4);
            As[row][q*4+0] = fmaxf(v.x, 0.0f); As[row][q*4+1] = fmaxf(v.y, 0.0f);
            As[row][q*4+2] = fmaxf(v.z, 0.0f); As[row][q*4+3] = fmaxf(v.w, 0.0f);
        }
#pragma unroll
        for (int jj = 0; jj < 2; jj++) {
            int id = tid + jj * 256;
            if (id < 24 * 16) {
                int row = id >> 4, q = id & 15;
                const float* src = (row < 22) ? (cfw + (size_t)row * HID)
                                              : (mkw + (size_t)(row - 22) * HID);
                float4 v = *(const float4*)(src + kc + q * 4);
                Ws[row][q*4+0] = v.x; Ws[row][q*4+1] = v.y;
                Ws[row][q*4+2] = v.z; Ws[row][q*4+3] = v.w;
            }
        }
        __syncthreads();
#pragma unroll
        for (int kk = 0; kk < 64; kk++) {
            float a = As[r][kk];
#pragma unroll
            for (int cc = 0; cc < 3; cc++) {
                int c = s + 8 * cc;
                acc[cc] += a * Ws[c][kk];
            }
        }
        __syncthreads();
    }
    int row = r0 + r;
#pragma unroll
    for (int cc = 0; cc < 3; cc++) {
        int c = s + 8 * cc;
        float b = (c < 22) ? cfb[c] : mkb[c - 22];
        float val = acc[cc] + b;
        if (c < 22) enc[(size_t)row * 22 + c] = val;
        else        mask[(size_t)row * 2 + (c - 22)] = val;
    }
}

// ======================= launch ==============================================================
extern "C" void kernel_launch(void* const* d_in, const int* in_sizes, int n_in,
                              void* d_out, int out_size)
{
    const float* feats = (const float*)d_in[0];
    const float* fc_w  = (const float*)d_in[1];
    const float* fc_b  = (const float*)d_in[2];
    const float* cls_w = (const float*)d_in[3];
    const float* cls_b = (const float*)d_in[4];
    const float* w_ih  = (const float*)d_in[5];
    const float* w_hh  = (const float*)d_in[6];
    const float* b_ih  = (const float*)d_in[7];
    const float* b_hh  = (const float*)d_in[8];
    const float* cf_w  = (const float*)d_in[9];
    const float* cf_b  = (const float*)d_in[10];
    const float* mk_w  = (const float*)d_in[11];
    const float* mk_b  = (const float*)d_in[12];

    float* out  = (float*)d_out;
    float* enc  = out;
    float* mask = out + 8192 * 22;
    float* xbuf = out + 8192 * 22 + 8192 * 2;
    float* vl   = xbuf + (size_t)ROWS * FEAT;

    float *gi_ptr, *hall_ptr, *gh_ptr;
    __nv_bfloat16 *fh, *fl, *xh, *xl, *wfh, *wfl, *wihh, *wihl, *whh_h, *whh_l, *hbh, *hbl;
    cudaGetSymbolAddress((void**)&gi_ptr, g_gi);
    cudaGetSymbolAddress((void**)&hall_ptr, g_hall);
    cudaGetSymbolAddress((void**)&gh_ptr, g_gh);
    cudaGetSymbolAddress((void**)&fh, g_fh);   cudaGetSymbolAddress((void**)&fl, g_fl);
    cudaGetSymbolAddress((void**)&xh, g_xh);   cudaGetSymbolAddress((void**)&xl, g_xl);
    cudaGetSymbolAddress((void**)&wfh, g_wfh); cudaGetSymbolAddress((void**)&wfl, g_wfl);
    cudaGetSymbolAddress((void**)&wihh, g_wih); cudaGetSymbolAddress((void**)&wihl, g_wil);
    cudaGetSymbolAddress((void**)&whh_h, g_whh); cudaGetSymbolAddress((void**)&whh_l, g_whl);
    cudaGetSymbolAddress((void**)&hbh, g_hbh);  cudaGetSymbolAddress((void**)&hbl, g_hbl);

    cudaFuncSetAttribute(mma_gemm<0>, cudaFuncAttributeMaxDynamicSharedMemorySize, MM_SMEM);
    cudaFuncSetAttribute(mma_gemm<1>, cudaFuncAttributeMaxDynamicSharedMemorySize, MM_SMEM);
    cudaFuncSetAttribute(gh_gemm, cudaFuncAttributeMaxDynamicSharedMemorySize, GH_SMEM);

    // 0. fp32 -> bf16 hi/lo converts
    convert_hilo<<<(ROWS * FEAT) / 1024, 256>>>(feats, fh, fl, ROWS * FEAT);
    convert_hilo<<<(FEAT * FEAT) / 1024, 256>>>(fc_w, wfh, wfl, FEAT * FEAT);
    convert_hilo<<<(GI_N * FEAT) / 1024, 256>>>(w_ih, wihh, wihl, GI_N * FEAT);
    convert_hilo<<<(GI_N * HID) / 1024, 256>>>(w_hh, whh_h, whh_l, GI_N * HID);

    // 1. fc GEMM (HMMA) + fused bias/relu/dropout + x fp32 + x bf16 hi/lo
    mma_gemm<0><<<dim3(FEAT / 128, ROWS / 128), 256, MM_SMEM>>>(
        fh, fl, wfh, wfl, fc_b, xbuf, xh, xl, FEAT, FEAT);

    // 2. vl_preds
    vl_kernel<<<ROWS / 32, 256>>>(xbuf, cls_w, cls_b, vl);

    // 3. gi = x @ w_ih^T + b_ih (HMMA)
    mma_gemm<1><<<dim3(GI_N / 128, ROWS / 128), 256, MM_SMEM>>>(
        xh, xl, wihh, wihl, b_ih, gi_ptr, nullptr, nullptr, FEAT, GI_N);

    // 4. zero h0 (fp32 + bf16 ping buffer 0)
    cudaMemsetAsync(hall_ptr, 0, (size_t)NSEQ * HID * sizeof(float));
    cudaMemsetAsync(hbh, 0, (size_t)NSEQ * HID * sizeof(__nv_bfloat16));
    cudaMemsetAsync(hbl, 0, (size_t)NSEQ * HID * sizeof(__nv_bfloat16));

    // 5. GRU scan: HMMA gh GEMM + elementwise gates per step
    for (int t = 0; t < NSTEP; t++) {
        const size_t po = (size_t)(t & 1) * NSEQ * HID;        // ping slot GEMM reads
        const size_t qo = (size_t)((t + 1) & 1) * NSEQ * HID;  // slot gates write
        gh_gemm<<<dim3(GI_N / 64, NSEQ / 64), 256, GH_SMEM>>>(
            hbh + po, hbl + po, whh_h, whh_l, gh_ptr);
        gate_kernel<<<NSEQ, 256>>>(gi_ptr, gh_ptr, b_hh, t, hbh + qo, hbl + qo);
    }

    // 6. enc/mask scores
    cf_kernel<<<ROWS / 32, 256>>>(hall_ptr + (size_t)NSEQ * HID,
                                  cf_w, cf_b, mk_w, mk_b, enc, mask);
}